// round 2
// baseline (speedup 1.0000x reference)
#include <cuda_runtime.h>

// ---------------------------------------------------------------------------
// MemristiveLinear collapses exactly to  y = x @ w + b  (512x512x512 fp32).
//   g_pos - g_neg = k_cond * w  (G_OFF cancels), K_V/k_cond scales divide out.
//
// Single fused kernel:
//   - 128 CTAs = (512/32 n-tiles) x (512/64 m-tiles), 512 threads.
//   - Intra-CTA split-K x4: quarter q (128 thr) computes the 64x32 tile over
//     K in [128q, 128q+128), partials reduced via smem + bias at the end.
//   - fma.rn.f32x2 (FFMA2) inner loop: accumulators paired over M so the A
//     operand pairs come free from LDS.128; B is stored PRE-DUPLICATED in
//     smem ({b,b}) in two 128B-contiguous arrays -> 3 conflict-free LDS.128
//     + 8 FFMA2 per k per thread, zero MOVs.
//   - Double-buffered smem, register-staged global prefetch.
//   - No device scratch, no second launch.
// ---------------------------------------------------------------------------

#define MD 512
#define ND 512
#define KD 512

#define TILE_M 64
#define TILE_N 32
#define NQ 4                 // intra-CTA split-K quarters
#define KQ (KD / NQ)         // 128
#define BK 8
#define NCHUNK (KQ / BK)     // 16
#define NTHREADS 512

union SmemU {
    struct {
        float xs[2][NQ][BK][64];     // [buf][q][k][m]        16 KB
        float wsA[2][NQ][BK][32];    // dup pairs n={4ng,4ng+1} 8 KB
        float wsB[2][NQ][BK][32];    // dup pairs n={4ng+2,4ng+3} 8 KB
    } t;
    float red[NQ][TILE_N][66];       // [q][n][m] (+2 pad, keeps 8B align) 33 KB
};

__device__ __forceinline__ void ffma2(unsigned long long& d,
                                      unsigned long long a,
                                      unsigned long long b) {
    asm("fma.rn.f32x2 %0, %1, %2, %0;" : "+l"(d) : "l"(a), "l"(b));
}

__global__ __launch_bounds__(NTHREADS, 1)
void fused_gemm_kernel(const float* __restrict__ X,
                       const float* __restrict__ W,
                       const float* __restrict__ Bias,
                       float* __restrict__ Y) {
    __shared__ SmemU sm;

    const int tid = threadIdx.x;
    const int q   = tid >> 7;        // split-K quarter 0..3
    const int qt  = tid & 127;
    const int mg  = qt >> 3;         // 0..15  (micro-tile M group, 4 rows)
    const int ng  = qt & 7;          // 0..7   (micro-tile N group, 4 cols)
    const int n0  = blockIdx.x * TILE_N;
    const int m0  = blockIdx.y * TILE_M;
    const int kq0 = q * KQ;

    // X loader: thread -> (m row, half of the 8 k's)
    const int xm  = qt & 63;
    const int xkh = qt >> 6;         // 0/1
    const float* xptr = X + (m0 + xm) * KD + kq0 + xkh * 4;

    // W loader: qt<64 -> (k row 0..7, n float4 0..7)
    const bool wload = (qt < 64);
    const int wk  = qt >> 3;
    const int wn4 = qt & 7;
    const float* wptr = W + (kq0 + wk) * ND + n0 + 4 * wn4;

    float4 xr, wr;

    unsigned long long acc[2][4];    // [m-pair p][n j]; f32x2 over (4mg+2p, 4mg+2p+1)
#pragma unroll
    for (int p = 0; p < 2; p++)
#pragma unroll
        for (int j = 0; j < 4; j++) acc[p][j] = 0ull;

#define GLOAD(c)                                                            \
    do {                                                                    \
        xr = *(const float4*)(xptr + (c) * BK);                             \
        if (wload) wr = *(const float4*)(wptr + (c) * BK * ND);             \
    } while (0)

#define STS(b)                                                              \
    do {                                                                    \
        sm.t.xs[b][q][xkh * 4 + 0][xm] = xr.x;                              \
        sm.t.xs[b][q][xkh * 4 + 1][xm] = xr.y;                              \
        sm.t.xs[b][q][xkh * 4 + 2][xm] = xr.z;                              \
        sm.t.xs[b][q][xkh * 4 + 3][xm] = xr.w;                              \
        if (wload) {                                                        \
            float4 dA = make_float4(wr.x, wr.x, wr.y, wr.y);                \
            float4 dB = make_float4(wr.z, wr.z, wr.w, wr.w);                \
            *(float4*)&sm.t.wsA[b][q][wk][4 * wn4] = dA;                    \
            *(float4*)&sm.t.wsB[b][q][wk][4 * wn4] = dB;                    \
        }                                                                   \
    } while (0)

    GLOAD(0);
    STS(0);
    __syncthreads();

#pragma unroll 2
    for (int c = 0; c < NCHUNK; c++) {
        const int buf = c & 1;
        if (c + 1 < NCHUNK) GLOAD(c + 1);

#pragma unroll
        for (int k = 0; k < BK; k++) {
            ulonglong2 av  = *(const ulonglong2*)&sm.t.xs[buf][q][k][4 * mg];
            ulonglong2 b01 = *(const ulonglong2*)&sm.t.wsA[buf][q][k][4 * ng];
            ulonglong2 b23 = *(const ulonglong2*)&sm.t.wsB[buf][q][k][4 * ng];
            ffma2(acc[0][0], av.x, b01.x);
            ffma2(acc[0][1], av.x, b01.y);
            ffma2(acc[0][2], av.x, b23.x);
            ffma2(acc[0][3], av.x, b23.y);
            ffma2(acc[1][0], av.y, b01.x);
            ffma2(acc[1][1], av.y, b01.y);
            ffma2(acc[1][2], av.y, b23.x);
            ffma2(acc[1][3], av.y, b23.y);
        }

        if (c + 1 < NCHUNK) STS(buf ^ 1);
        __syncthreads();
    }

    // Dump partials to reduce buffer (aliases tile smem; compute fully done
    // at the loop's trailing barrier). red layout [q][n][m], m contiguous so
    // each f32x2 acc is one aligned STS.64.
#pragma unroll
    for (int p = 0; p < 2; p++)
#pragma unroll
        for (int j = 0; j < 4; j++)
            *(unsigned long long*)&sm.red[q][4 * ng + j][4 * mg + 2 * p] =
                acc[p][j];
    __syncthreads();

    // Reduce 4 quarters + bias, store. Thread -> one float4 of output.
    const int fm  = tid >> 3;        // 0..63
    const int fn4 = tid & 7;         // 0..7
    const float4 bb = *(const float4*)(Bias + n0 + 4 * fn4);
    float s0 = 0.f, s1 = 0.f, s2 = 0.f, s3 = 0.f;
#pragma unroll
    for (int qq = 0; qq < NQ; qq++) {
        s0 += sm.red[qq][4 * fn4 + 0][fm];
        s1 += sm.red[qq][4 * fn4 + 1][fm];
        s2 += sm.red[qq][4 * fn4 + 2][fm];
        s3 += sm.red[qq][4 * fn4 + 3][fm];
    }
    float4 r;
    r.x = s0 + bb.x;
    r.y = s1 + bb.y;
    r.z = s2 + bb.z;
    r.w = s3 + bb.w;
    *(float4*)(Y + (m0 + fm) * ND + n0 + 4 * fn4) = r;

#undef GLOAD
#undef STS
}

extern "C" void kernel_launch(void* const* d_in, const int* in_sizes, int n_in,
                              void* d_out, int out_size) {
    const float* x = (const float*)d_in[0];  // [512, 512]
    const float* w = (const float*)d_in[1];  // [512, 512]
    const float* b = (const float*)d_in[2];  // [512]
    float* y = (float*)d_out;                // [512, 512]

    dim3 grid(ND / TILE_N, MD / TILE_M);     // (16, 8) = 128 CTAs
    fused_gemm_kernel<<<grid, NTHREADS>>>(x, w, b, y);
}

// round 4
// speedup vs baseline: 1.4579x; 1.4579x over previous
#include <cuda_runtime.h>
#include <cuda_bf16.h>
#include <cstdint>

// ---------------------------------------------------------------------------
// MemristiveLinear collapses exactly to  y = x @ w + b  (512x512x512 fp32).
//
// tcgen05 (kind::f16) split-precision GEMM:
//   x = xh + xl, w = wh + wl (bf16 hi/lo);  y ~= xh@wh + xh@wl + xl@wh  (+b)
//
// The harness compiles BOTH a generic compute_103 PTX pass and an sm_103a
// pass. tcgen05 is an arch-specific ('a') feature, so all tcgen05 asm is
// guarded by the arch-feature macros; the generic pass gets a plain fp32
// fallback body (correct, never expected to run — the driver prefers the
// exact-match sm_103a cubin).
// ---------------------------------------------------------------------------

#if defined(__CUDA_ARCH_FEAT_SM103_ALL) || defined(__CUDA_ARCH_FEAT_SM100_ALL) || \
    defined(__CUDA_ARCH_FEAT_SM101_ALL) || defined(__CUDA_ARCH_SPECIFIC__) ||     \
    defined(__CUDA_ARCH_FAMILY_SPECIFIC__)
#define TC_OK 1
#else
#define TC_OK 0
#endif

#define MD 512
#define ND 512
#define KD 512

// bf16 scratch, stored as uint4 (8 bf16 each) for vector access.
__device__ uint4 gXH[MD * KD / 8];
__device__ uint4 gXL[MD * KD / 8];
__device__ uint4 gWTH[ND * KD / 8];
__device__ uint4 gWTL[ND * KD / 8];

// ---------------------------------------------------------------------------
// Convert kernel (plain ops, compiles on every target)
// ---------------------------------------------------------------------------
__device__ __forceinline__ void split_pair(float a, float b,
                                           unsigned& hp, unsigned& lp) {
    unsigned uha = __bfloat16_as_ushort(__float2bfloat16_rn(a));
    unsigned uhb = __bfloat16_as_ushort(__float2bfloat16_rn(b));
    float ra = a - __uint_as_float(uha << 16);
    float rb = b - __uint_as_float(uhb << 16);
    unsigned ula = __bfloat16_as_ushort(__float2bfloat16_rn(ra));
    unsigned ulb = __bfloat16_as_ushort(__float2bfloat16_rn(rb));
    hp = uha | (uhb << 16);
    lp = ula | (ulb << 16);
}

__global__ __launch_bounds__(256)
void convert_kernel(const float* __restrict__ X, const float* __restrict__ W) {
    __shared__ float sm[64][65];
    const int t = threadIdx.x;
    const int b = blockIdx.x;

    if (b < 64) {
        // X -> XH/XL (same layout, [m][k])
        const float4* X4 = (const float4*)X;
        uint2* XH2 = (uint2*)gXH;
        uint2* XL2 = (uint2*)gXL;
#pragma unroll
        for (int j = 0; j < 4; j++) {
            const int f4 = b * 1024 + j * 256 + t;
            float4 v = X4[f4];
            unsigned h01, l01, h23, l23;
            split_pair(v.x, v.y, h01, l01);
            split_pair(v.z, v.w, h23, l23);
            XH2[f4] = make_uint2(h01, h23);
            XL2[f4] = make_uint2(l01, l23);
        }
    } else {
        // W[k][n] -> WT[n][k] hi/lo via 64x64 smem transpose tile
        const int bb = b - 64;
        const int tk = bb >> 3, tn = bb & 7;
        const int r = t >> 2, q4 = t & 3;
        const float* wrow = W + (tk * 64 + r) * ND + tn * 64;
#pragma unroll
        for (int j = 0; j < 4; j++) {
            float4 v = *(const float4*)(wrow + (q4 * 4 + j) * 4);
            sm[r][(q4 * 4 + j) * 4 + 0] = v.x;
            sm[r][(q4 * 4 + j) * 4 + 1] = v.y;
            sm[r][(q4 * 4 + j) * 4 + 2] = v.z;
            sm[r][(q4 * 4 + j) * 4 + 3] = v.w;
        }
        __syncthreads();
        const int c = t >> 2, qr = t & 3;
        uint2* WH2 = (uint2*)gWTH;
        uint2* WL2 = (uint2*)gWTL;
        const int outbase = ((tn * 64 + c) * KD + tk * 64 + qr * 16) / 4;
#pragma unroll
        for (int g = 0; g < 4; g++) {
            float v0 = sm[qr * 16 + 4 * g + 0][c];
            float v1 = sm[qr * 16 + 4 * g + 1][c];
            float v2 = sm[qr * 16 + 4 * g + 2][c];
            float v3 = sm[qr * 16 + 4 * g + 3][c];
            unsigned h01, l01, h23, l23;
            split_pair(v0, v1, h01, l01);
            split_pair(v2, v3, h23, l23);
            WH2[outbase + g] = make_uint2(h01, h23);
            WL2[outbase + g] = make_uint2(l01, l23);
        }
    }
}

// ---------------------------------------------------------------------------
// GEMM kernel: tcgen05 on arch-specific targets, fp32 tiled fallback else
// ---------------------------------------------------------------------------
#define SWZ(o) ((o) ^ (((o) >> 3) & 0x70))
#define DESC_BASE 0x4000404000010000ull
#define MK_DESC(addr) (DESC_BASE | (((unsigned long long)((addr) >> 4)) & 0x3FFF))
// kind::f16 idesc: F32 acc, BF16 a/b, N=64, M=128
#define IDESC ((1u << 4) | (1u << 7) | (1u << 10) | (8u << 17) | (8u << 24))

__device__ __forceinline__ uint32_t s2u(const void* p) {
    uint32_t a;
    asm("{ .reg .u64 t; cvta.to.shared.u64 t, %1; cvt.u32.u64 %0, t; }"
        : "=r"(a) : "l"(p));
    return a;
}

#if TC_OK
__device__ __forceinline__ void mma_f16_ss(uint32_t d, unsigned long long ad,
                                           unsigned long long bd,
                                           uint32_t idesc, uint32_t en) {
    asm volatile(
        "{\n\t.reg .pred p;\n\tsetp.ne.u32 p, %5, 0;\n\t"
        "tcgen05.mma.cta_group::1.kind::f16 [%0], %1, %2, %3, {%4, %4, %4, %4}, p;\n\t}"
        :: "r"(d), "l"(ad), "l"(bd), "r"(idesc), "r"(0u), "r"(en)
        : "memory");
}

#define MBAR_INIT(a) \
    asm volatile("mbarrier.init.shared.b64 [%0], %1;" :: "r"(a), "r"(1u) : "memory")

#define MBAR_WAITP(a, ph) do {                                                \
    unsigned _m = (a), _p = (ph), _d;                                         \
    asm volatile("{\n\t.reg .pred p;\n\t"                                     \
        "mbarrier.try_wait.parity.acquire.cta.shared::cta.b64 p, [%1], %2;\n\t" \
        "selp.b32 %0, 1, 0, p;\n\t}" : "=r"(_d) : "r"(_m), "r"(_p) : "memory"); \
    if (!_d) {                                                                \
        asm volatile("{\n\t.reg .pred P1;\n\t"                                \
            "WL_%=:\n\t"                                                      \
            "mbarrier.try_wait.parity.acquire.cta.shared::cta.b64 P1, [%0], %1, 0x989680;\n\t" \
            "@P1 bra.uni WD_%=;\n\t"                                          \
            "bra.uni WL_%=;\n\t"                                              \
            "WD_%=:\n\t}" :: "r"(_m), "r"(_p) : "memory");                    \
    }                                                                         \
} while (0)

#define TC_COMMIT(a) \
    asm volatile("tcgen05.commit.cta_group::1.mbarrier::arrive::one.shared::cluster.b64 [%0];" \
                 :: "r"(a) : "memory")

#define LDTM_X32(r, addr)                                                     \
    asm volatile("tcgen05.ld.sync.aligned.32x32b.x32.b32 "                    \
        "{%0, %1, %2, %3, %4, %5, %6, %7, "                                   \
        " %8, %9, %10, %11, %12, %13, %14, %15, "                             \
        " %16, %17, %18, %19, %20, %21, %22, %23, "                           \
        " %24, %25, %26, %27, %28, %29, %30, %31}, [%32];"                    \
        : "=r"((r)[0]),  "=r"((r)[1]),  "=r"((r)[2]),  "=r"((r)[3]),          \
          "=r"((r)[4]),  "=r"((r)[5]),  "=r"((r)[6]),  "=r"((r)[7]),          \
          "=r"((r)[8]),  "=r"((r)[9]),  "=r"((r)[10]), "=r"((r)[11]),         \
          "=r"((r)[12]), "=r"((r)[13]), "=r"((r)[14]), "=r"((r)[15]),         \
          "=r"((r)[16]), "=r"((r)[17]), "=r"((r)[18]), "=r"((r)[19]),         \
          "=r"((r)[20]), "=r"((r)[21]), "=r"((r)[22]), "=r"((r)[23]),         \
          "=r"((r)[24]), "=r"((r)[25]), "=r"((r)[26]), "=r"((r)[27]),         \
          "=r"((r)[28]), "=r"((r)[29]), "=r"((r)[30]), "=r"((r)[31])          \
        : "r"(addr))
#endif  // TC_OK

// smem layout (relative to 1024-aligned base):
//   0: tmem ptr | 8: mbar0 | 16: mbar1 | 256: bias_s[64]
//   1024 + buf*49152: { Ah 16K, Al 16K, Bh 8K, Bl 8K }
#define BUF_STRIDE 49152
#define SMEM_DYN 100480

__global__ __launch_bounds__(512, 1)
void gemm_kernel(const float* __restrict__ X, const float* __restrict__ W,
                 const float* __restrict__ Bias, float* __restrict__ Y) {
    extern __shared__ char dsm[];
    const int tid = threadIdx.x;
    const int n0 = blockIdx.x * 64;
    const int m0 = blockIdx.y * 128;

#if TC_OK
    const uint32_t raw = s2u(dsm);
    const uint32_t base = (raw + 1023u) & ~1023u;
    char* dbase = dsm + (base - raw);

    const int wid = tid >> 5;
    const int lid = tid & 31;

    float* bias_s = (float*)(dbase + 256);
    if (tid < 16)
        ((float4*)bias_s)[tid] = ((const float4*)(Bias + n0))[tid];

    if (wid == 0)
        asm volatile(
            "tcgen05.alloc.cta_group::1.sync.aligned.shared::cta.b32 [%0], %1;"
            :: "r"(base), "r"(512u) : "memory");
    if (tid == 0) {
        MBAR_INIT(base + 8);
        MBAR_INIT(base + 16);
    }
    __syncthreads();
    uint32_t tmem;
    asm("ld.shared.b32 %0, [%1];" : "=r"(tmem) : "r"(base));

    int ph0 = 0, ph1 = 0;

#pragma unroll
    for (int c = 0; c < 8; c++) {
        const int buf = c & 1;
        const uint32_t bufb = base + 1024 + buf * BUF_STRIDE;
        char* bufp = dbase + 1024 + buf * BUF_STRIDE;

        if (c >= 2) {
            if (buf == 0) { MBAR_WAITP(base + 8, ph0);  ph0 ^= 1; }
            else          { MBAR_WAITP(base + 16, ph1); ph1 ^= 1; }
        }

        const int kc8 = c * 8;  // uint4 offset within a 512-elem row
#pragma unroll
        for (int j = 0; j < 2; j++) {
            const int u = j * 512 + tid;
            const int row = u >> 3, seg = u & 7;
            uint4 vh = gXH[(m0 + row) * 64 + kc8 + seg];
            uint4 vl = gXL[(m0 + row) * 64 + kc8 + seg];
            const int off = SWZ(row * 128 + seg * 16);
            *(uint4*)(bufp + off) = vh;
            *(uint4*)(bufp + 16384 + off) = vl;
        }
        {
            const int row = tid >> 3, seg = tid & 7;
            uint4 vh = gWTH[(n0 + row) * 64 + kc8 + seg];
            uint4 vl = gWTL[(n0 + row) * 64 + kc8 + seg];
            const int off = SWZ(row * 128 + seg * 16);
            *(uint4*)(bufp + 32768 + off) = vh;
            *(uint4*)(bufp + 40960 + off) = vl;
        }
        asm volatile("fence.proxy.async.shared::cta;" ::: "memory");
        __syncthreads();

        if (tid == 0) {
            const unsigned long long ah = MK_DESC(bufb);
            const unsigned long long al = MK_DESC(bufb + 16384);
            const unsigned long long bh = MK_DESC(bufb + 32768);
            const unsigned long long bl = MK_DESC(bufb + 40960);
#pragma unroll
            for (int ks = 0; ks < 4; ks++) {
                mma_f16_ss(tmem, ah + 2 * ks, bh + 2 * ks, IDESC,
                           (c == 0 && ks == 0) ? 0u : 1u);
                mma_f16_ss(tmem, ah + 2 * ks, bl + 2 * ks, IDESC, 1u);
                mma_f16_ss(tmem, al + 2 * ks, bh + 2 * ks, IDESC, 1u);
            }
            TC_COMMIT(base + 8 + buf * 8);
        }
    }

    MBAR_WAITP(base + 8, ph0);
    MBAR_WAITP(base + 16, ph1);
    asm volatile("tcgen05.fence::after_thread_sync;" ::: "memory");

    if (wid < 4) {
        uint32_t d0[32], d1[32];
        LDTM_X32(d0, tmem);
        LDTM_X32(d1, tmem + 32);
        asm volatile("tcgen05.wait::ld.sync.aligned;" ::: "memory");

        float* yr = Y + (m0 + wid * 32 + lid) * ND + n0;
#pragma unroll
        for (int g = 0; g < 8; g++) {
            float4 bb = *(float4*)&bias_s[4 * g];
            float4 r;
            r.x = __uint_as_float(d0[4 * g + 0]) + bb.x;
            r.y = __uint_as_float(d0[4 * g + 1]) + bb.y;
            r.z = __uint_as_float(d0[4 * g + 2]) + bb.z;
            r.w = __uint_as_float(d0[4 * g + 3]) + bb.w;
            *(float4*)(yr + 4 * g) = r;
            float4 bb2 = *(float4*)&bias_s[32 + 4 * g];
            float4 r2;
            r2.x = __uint_as_float(d1[4 * g + 0]) + bb2.x;
            r2.y = __uint_as_float(d1[4 * g + 1]) + bb2.y;
            r2.z = __uint_as_float(d1[4 * g + 2]) + bb2.z;
            r2.w = __uint_as_float(d1[4 * g + 3]) + bb2.w;
            *(float4*)(yr + 32 + 4 * g) = r2;
        }
    }

    __syncthreads();
    if (wid == 0) {
        asm volatile("tcgen05.relinquish_alloc_permit.cta_group::1.sync.aligned;");
        asm volatile("tcgen05.dealloc.cta_group::1.sync.aligned.b32 %0, %1;"
                     :: "r"(tmem), "r"(512u));
    }
#else
    // -------- generic-target fallback: fp32 smem-tiled GEMM (correct) ------
    float* xs = (float*)dsm;             // [64 k][128 m]
    float* ws = xs + 64 * 128;           // [64 k][64 n]

    const int mq = tid >> 4;             // 0..31 -> 4 m rows
    const int nq = tid & 15;             // 0..15 -> 4 n cols
    float acc[4][4];
#pragma unroll
    for (int i = 0; i < 4; i++)
#pragma unroll
        for (int j = 0; j < 4; j++) acc[i][j] = 0.f;

    for (int kb = 0; kb < KD; kb += 64) {
        __syncthreads();
        // load X tile: 128 m x 64 k, transpose to [k][m]
#pragma unroll
        for (int j = 0; j < 4; j++) {
            const int u = j * 512 + tid;            // 2048 float4 slots
            const int row = u >> 4, kq4 = u & 15;   // row 0..127, k-quad
            float4 v = *(const float4*)(X + (m0 + row) * KD + kb + 4 * kq4);
            xs[(4 * kq4 + 0) * 128 + row] = v.x;
            xs[(4 * kq4 + 1) * 128 + row] = v.y;
            xs[(4 * kq4 + 2) * 128 + row] = v.z;
            xs[(4 * kq4 + 3) * 128 + row] = v.w;
        }
        // load W tile: 64 k x 64 n, natural
        {
            const int row = tid >> 4, nq4 = tid & 15;  // k row, n-quad
            float4 v = *(const float4*)(W + (kb + row) * ND + n0 + 4 * nq4);
            *(float4*)&ws[row * 64 + 4 * nq4] = v;
        }
        __syncthreads();

#pragma unroll 8
        for (int k = 0; k < 64; k++) {
            float4 a = *(float4*)&xs[k * 128 + 4 * mq];
            float4 b = *(float4*)&ws[k * 64 + 4 * nq];
            const float av[4] = {a.x, a.y, a.z, a.w};
            const float bv[4] = {b.x, b.y, b.z, b.w};
#pragma unroll
            for (int i = 0; i < 4; i++)
#pragma unroll
                for (int j = 0; j < 4; j++) acc[i][j] += av[i] * bv[j];
        }
    }

    const float4 bb = *(const float4*)(Bias + n0 + 4 * nq);
#pragma unroll
    for (int i = 0; i < 4; i++) {
        float4 r;
        r.x = acc[i][0] + bb.x;
        r.y = acc[i][1] + bb.y;
        r.z = acc[i][2] + bb.z;
        r.w = acc[i][3] + bb.w;
        *(float4*)(Y + (m0 + 4 * mq + i) * ND + n0 + 4 * nq) = r;
    }
#endif
}

extern "C" void kernel_launch(void* const* d_in, const int* in_sizes, int n_in,
                              void* d_out, int out_size) {
    const float* x = (const float*)d_in[0];  // [512, 512]
    const float* w = (const float*)d_in[1];  // [512, 512]
    const float* b = (const float*)d_in[2];  // [512]
    float* y = (float*)d_out;                // [512, 512]

    static bool attr_done = false;
    if (!attr_done) {
        cudaFuncSetAttribute(gemm_kernel,
                             cudaFuncAttributeMaxDynamicSharedMemorySize,
                             SMEM_DYN);
        attr_done = true;
    }

    convert_kernel<<<128, 256>>>(x, w);
    dim3 grid(ND / 64, MD / 128);            // (8, 4) = 32 CTAs
    gemm_kernel<<<grid, 512, SMEM_DYN>>>(x, w, b, y);
}

// round 5
// speedup vs baseline: 1.6525x; 1.1335x over previous
#include <cuda_runtime.h>
#include <cuda_bf16.h>
#include <cstdint>

// ---------------------------------------------------------------------------
// MemristiveLinear collapses exactly to  y = x @ w + b  (512x512x512 fp32).
//
// tcgen05 (kind::f16) split-precision GEMM:
//   x = xh + xl, w = wh + wl (bf16 hi/lo);  y ~= xh@wh + xh@wl + xl@wh  (+b)
//
// R5: pipeline overhaul of the R4 kernel (which was latency-serialized):
//   - register-prefetch next chunk's global loads (overlap L2 latency w/ MMA)
//   - single __syncthreads per chunk (mbarrier guards buffer reuse)
//   - N-tile 32 (idesc 0x8080490, exact test_mma.cu constant), 64 CTAs
// All tcgen05 asm guarded for the arch-specific pass; generic pass gets a
// correct fp32 fallback (never runs; driver loads the sm_103a cubin).
// ---------------------------------------------------------------------------

#if defined(__CUDA_ARCH_FEAT_SM103_ALL) || defined(__CUDA_ARCH_FEAT_SM100_ALL) || \
    defined(__CUDA_ARCH_FEAT_SM101_ALL) || defined(__CUDA_ARCH_SPECIFIC__) ||     \
    defined(__CUDA_ARCH_FAMILY_SPECIFIC__)
#define TC_OK 1
#else
#define TC_OK 0
#endif

#define MD 512
#define ND 512
#define KD 512

// bf16 scratch, stored as uint4 (8 bf16 each) for vector access.
__device__ uint4 gXH[MD * KD / 8];
__device__ uint4 gXL[MD * KD / 8];
__device__ uint4 gWTH[ND * KD / 8];
__device__ uint4 gWTL[ND * KD / 8];

// ---------------------------------------------------------------------------
// Convert kernel (plain ops, compiles on every target)
// ---------------------------------------------------------------------------
__device__ __forceinline__ void split_pair(float a, float b,
                                           unsigned& hp, unsigned& lp) {
    unsigned uha = __bfloat16_as_ushort(__float2bfloat16_rn(a));
    unsigned uhb = __bfloat16_as_ushort(__float2bfloat16_rn(b));
    float ra = a - __uint_as_float(uha << 16);
    float rb = b - __uint_as_float(uhb << 16);
    unsigned ula = __bfloat16_as_ushort(__float2bfloat16_rn(ra));
    unsigned ulb = __bfloat16_as_ushort(__float2bfloat16_rn(rb));
    hp = uha | (uhb << 16);
    lp = ula | (ulb << 16);
}

__global__ __launch_bounds__(256)
void convert_kernel(const float* __restrict__ X, const float* __restrict__ W) {
    __shared__ float sm[64][65];
    const int t = threadIdx.x;
    const int b = blockIdx.x;

    if (b < 64) {
        // X -> XH/XL (same layout, [m][k])
        const float4* X4 = (const float4*)X;
        uint2* XH2 = (uint2*)gXH;
        uint2* XL2 = (uint2*)gXL;
#pragma unroll
        for (int j = 0; j < 4; j++) {
            const int f4 = b * 1024 + j * 256 + t;
            float4 v = X4[f4];
            unsigned h01, l01, h23, l23;
            split_pair(v.x, v.y, h01, l01);
            split_pair(v.z, v.w, h23, l23);
            XH2[f4] = make_uint2(h01, h23);
            XL2[f4] = make_uint2(l01, l23);
        }
    } else {
        // W[k][n] -> WT[n][k] hi/lo via 64x64 smem transpose tile
        const int bb = b - 64;
        const int tk = bb >> 3, tn = bb & 7;
        const int r = t >> 2, q4 = t & 3;
        const float* wrow = W + (tk * 64 + r) * ND + tn * 64;
#pragma unroll
        for (int j = 0; j < 4; j++) {
            float4 v = *(const float4*)(wrow + (q4 * 4 + j) * 4);
            sm[r][(q4 * 4 + j) * 4 + 0] = v.x;
            sm[r][(q4 * 4 + j) * 4 + 1] = v.y;
            sm[r][(q4 * 4 + j) * 4 + 2] = v.z;
            sm[r][(q4 * 4 + j) * 4 + 3] = v.w;
        }
        __syncthreads();
        const int c = t >> 2, qr = t & 3;
        uint2* WH2 = (uint2*)gWTH;
        uint2* WL2 = (uint2*)gWTL;
        const int outbase = ((tn * 64 + c) * KD + tk * 64 + qr * 16) / 4;
#pragma unroll
        for (int g = 0; g < 4; g++) {
            float v0 = sm[qr * 16 + 4 * g + 0][c];
            float v1 = sm[qr * 16 + 4 * g + 1][c];
            float v2 = sm[qr * 16 + 4 * g + 2][c];
            float v3 = sm[qr * 16 + 4 * g + 3][c];
            unsigned h01, l01, h23, l23;
            split_pair(v0, v1, h01, l01);
            split_pair(v2, v3, h23, l23);
            WH2[outbase + g] = make_uint2(h01, h23);
            WL2[outbase + g] = make_uint2(l01, l23);
        }
    }
}

// ---------------------------------------------------------------------------
// GEMM kernel: tcgen05 on arch-specific targets, fp32 fallback else
// ---------------------------------------------------------------------------
#define SWZ(o) ((o) ^ (((o) >> 3) & 0x70))
#define DESC_BASE 0x4000404000010000ull
#define MK_DESC(addr) (DESC_BASE | (((unsigned long long)((addr) >> 4)) & 0x3FFF))
// kind::f16 idesc: F32 acc, BF16 a/b, M=128, N=32  (== test_mma.cu 0x8080490)
#define IDESC ((1u << 4) | (1u << 7) | (1u << 10) | (4u << 17) | (8u << 24))

__device__ __forceinline__ uint32_t s2u(const void* p) {
    uint32_t a;
    asm("{ .reg .u64 t; cvta.to.shared.u64 t, %1; cvt.u32.u64 %0, t; }"
        : "=r"(a) : "l"(p));
    return a;
}

#if TC_OK
__device__ __forceinline__ void mma_f16_ss(uint32_t d, unsigned long long ad,
                                           unsigned long long bd,
                                           uint32_t idesc, uint32_t en) {
    asm volatile(
        "{\n\t.reg .pred p;\n\tsetp.ne.u32 p, %5, 0;\n\t"
        "tcgen05.mma.cta_group::1.kind::f16 [%0], %1, %2, %3, {%4, %4, %4, %4}, p;\n\t}"
        :: "r"(d), "l"(ad), "l"(bd), "r"(idesc), "r"(0u), "r"(en)
        : "memory");
}

#define MBAR_INIT(a) \
    asm volatile("mbarrier.init.shared.b64 [%0], %1;" :: "r"(a), "r"(1u) : "memory")

#define MBAR_WAITP(a, ph) do {                                                \
    unsigned _m = (a), _p = (ph), _d;                                         \
    asm volatile("{\n\t.reg .pred p;\n\t"                                     \
        "mbarrier.try_wait.parity.acquire.cta.shared::cta.b64 p, [%1], %2;\n\t" \
        "selp.b32 %0, 1, 0, p;\n\t}" : "=r"(_d) : "r"(_m), "r"(_p) : "memory"); \
    if (!_d) {                                                                \
        asm volatile("{\n\t.reg .pred P1;\n\t"                                \
            "WL_%=:\n\t"                                                      \
            "mbarrier.try_wait.parity.acquire.cta.shared::cta.b64 P1, [%0], %1, 0x989680;\n\t" \
            "@P1 bra.uni WD_%=;\n\t"                                          \
            "bra.uni WL_%=;\n\t"                                              \
            "WD_%=:\n\t}" :: "r"(_m), "r"(_p) : "memory");                    \
    }                                                                         \
} while (0)

#define TC_COMMIT(a) \
    asm volatile("tcgen05.commit.cta_group::1.mbarrier::arrive::one.shared::cluster.b64 [%0];" \
                 :: "r"(a) : "memory")

#define LDTM_X32(r, addr)                                                     \
    asm volatile("tcgen05.ld.sync.aligned.32x32b.x32.b32 "                    \
        "{%0, %1, %2, %3, %4, %5, %6, %7, "                                   \
        " %8, %9, %10, %11, %12, %13, %14, %15, "                             \
        " %16, %17, %18, %19, %20, %21, %22, %23, "                           \
        " %24, %25, %26, %27, %28, %29, %30, %31}, [%32];"                    \
        : "=r"((r)[0]),  "=r"((r)[1]),  "=r"((r)[2]),  "=r"((r)[3]),          \
          "=r"((r)[4]),  "=r"((r)[5]),  "=r"((r)[6]),  "=r"((r)[7]),          \
          "=r"((r)[8]),  "=r"((r)[9]),  "=r"((r)[10]), "=r"((r)[11]),         \
          "=r"((r)[12]), "=r"((r)[13]), "=r"((r)[14]), "=r"((r)[15]),         \
          "=r"((r)[16]), "=r"((r)[17]), "=r"((r)[18]), "=r"((r)[19]),         \
          "=r"((r)[20]), "=r"((r)[21]), "=r"((r)[22]), "=r"((r)[23]),         \
          "=r"((r)[24]), "=r"((r)[25]), "=r"((r)[26]), "=r"((r)[27]),         \
          "=r"((r)[28]), "=r"((r)[29]), "=r"((r)[30]), "=r"((r)[31])          \
        : "r"(addr))
#endif  // TC_OK

// smem layout (relative to 1024-aligned base):
//   0: tmem ptr | 8: mbar0 | 16: mbar1 | 256: bias_s[32]
//   1024 + buf*40960: { Ah 16K, Al 16K, Bh 4K, Bl 4K }
#define BUF_STRIDE 40960
#define SMEM_DYN 84992

__global__ __launch_bounds__(512, 1)
void gemm_kernel(const float* __restrict__ X, const float* __restrict__ W,
                 const float* __restrict__ Bias, float* __restrict__ Y) {
    extern __shared__ char dsm[];
    const int tid = threadIdx.x;
    const int n0 = blockIdx.x * 32;
    const int m0 = blockIdx.y * 128;

#if TC_OK
    const uint32_t raw = s2u(dsm);
    const uint32_t base = (raw + 1023u) & ~1023u;
    char* dbase = dsm + (base - raw);

    const int wid = tid >> 5;
    const int lid = tid & 31;

    float* bias_s = (float*)(dbase + 256);
    if (tid < 8)
        ((float4*)bias_s)[tid] = ((const float4*)(Bias + n0))[tid];

    if (wid == 0)
        asm volatile(
            "tcgen05.alloc.cta_group::1.sync.aligned.shared::cta.b32 [%0], %1;"
            :: "r"(base), "r"(64u) : "memory");
    if (tid == 0) {
        MBAR_INIT(base + 8);
        MBAR_INIT(base + 16);
    }
    __syncthreads();
    uint32_t tmem;
    asm("ld.shared.b32 %0, [%1];" : "=r"(tmem) : "r"(base));

    // Per-thread load slots.
    //   A: two uint4 each for hi/lo (rows u>>3, segs u&7, u = j*512+tid)
    //   B: warps 0..7 (tid<256): one uint4 each hi/lo (row tid>>3, seg tid&7)
    const int ar0 = tid >> 3,           as0 = tid & 7;
    const int ar1 = (512 + tid) >> 3,   as1 = tid & 7;
    const bool bload = (tid < 256);
    const int br = tid >> 3, bs = tid & 7;
    const int aoff0 = SWZ(ar0 * 128 + as0 * 16);
    const int aoff1 = SWZ(ar1 * 128 + as1 * 16);
    const int boff  = SWZ(br * 128 + bs * 16);

    uint4 vah0, vah1, val0, val1, vbh, vbl;

#define GLOAD(c)                                                             \
    do {                                                                     \
        const int kc8 = (c) * 8;                                             \
        vah0 = gXH[(m0 + ar0) * 64 + kc8 + as0];                             \
        vah1 = gXH[(m0 + ar1) * 64 + kc8 + as1];                             \
        val0 = gXL[(m0 + ar0) * 64 + kc8 + as0];                             \
        val1 = gXL[(m0 + ar1) * 64 + kc8 + as1];                             \
        if (bload) {                                                         \
            vbh = gWTH[(n0 + br) * 64 + kc8 + bs];                           \
            vbl = gWTL[(n0 + br) * 64 + kc8 + bs];                           \
        }                                                                    \
    } while (0)

    GLOAD(0);

    int ph0 = 0, ph1 = 0;

#pragma unroll
    for (int c = 0; c < 8; c++) {
        const int buf = c & 1;
        const uint32_t bufb = base + 1024 + buf * BUF_STRIDE;
        char* bufp = dbase + 1024 + buf * BUF_STRIDE;

        // Guard smem buffer reuse: MMA(c-2) must be complete.
        if (c >= 2) {
            if (buf == 0) { MBAR_WAITP(base + 8, ph0);  ph0 ^= 1; }
            else          { MBAR_WAITP(base + 16, ph1); ph1 ^= 1; }
        }

        // Stage current chunk into smem (data prefetched last iteration).
        *(uint4*)(bufp + aoff0) = vah0;
        *(uint4*)(bufp + aoff1) = vah1;
        *(uint4*)(bufp + 16384 + aoff0) = val0;
        *(uint4*)(bufp + 16384 + aoff1) = val1;
        if (bload) {
            *(uint4*)(bufp + 32768 + boff) = vbh;
            *(uint4*)(bufp + 36864 + boff) = vbl;
        }

        // Prefetch next chunk while MMA(c) + barriers run.
        if (c + 1 < 8) GLOAD(c + 1);

        asm volatile("fence.proxy.async.shared::cta;" ::: "memory");
        __syncthreads();

        if (tid == 0) {
            const unsigned long long ah = MK_DESC(bufb);
            const unsigned long long al = MK_DESC(bufb + 16384);
            const unsigned long long bh = MK_DESC(bufb + 32768);
            const unsigned long long bl = MK_DESC(bufb + 36864);
#pragma unroll
            for (int ks = 0; ks < 4; ks++) {
                mma_f16_ss(tmem, ah + 2 * ks, bh + 2 * ks, IDESC,
                           (c == 0 && ks == 0) ? 0u : 1u);
                mma_f16_ss(tmem, ah + 2 * ks, bl + 2 * ks, IDESC, 1u);
                mma_f16_ss(tmem, al + 2 * ks, bh + 2 * ks, IDESC, 1u);
            }
            TC_COMMIT(base + 8 + buf * 8);
        }
        // No trailing sync: next iteration's mbarrier wait + the pre-dispatch
        // sync provide all required ordering (threads can't overwrite buf(c)
        // before passing the c+1 sync, which tid0 reaches only post-dispatch).
    }

    MBAR_WAITP(base + 8, ph0);
    MBAR_WAITP(base + 16, ph1);
    asm volatile("tcgen05.fence::after_thread_sync;" ::: "memory");

    if (wid < 4) {
        uint32_t d0[32];
        LDTM_X32(d0, tmem);
        asm volatile("tcgen05.wait::ld.sync.aligned;" ::: "memory");

        float* yr = Y + (m0 + wid * 32 + lid) * ND + n0;
#pragma unroll
        for (int g = 0; g < 8; g++) {
            float4 bb = *(float4*)&bias_s[4 * g];
            float4 r;
            r.x = __uint_as_float(d0[4 * g + 0]) + bb.x;
            r.y = __uint_as_float(d0[4 * g + 1]) + bb.y;
            r.z = __uint_as_float(d0[4 * g + 2]) + bb.z;
            r.w = __uint_as_float(d0[4 * g + 3]) + bb.w;
            *(float4*)(yr + 4 * g) = r;
        }
    }

    __syncthreads();
    if (wid == 0) {
        asm volatile("tcgen05.relinquish_alloc_permit.cta_group::1.sync.aligned;");
        asm volatile("tcgen05.dealloc.cta_group::1.sync.aligned.b32 %0, %1;"
                     :: "r"(tmem), "r"(64u));
    }
#undef GLOAD
#else
    // -------- generic-target fallback: fp32 smem-tiled GEMM (correct) ------
    float* xs = (float*)dsm;             // [64 k][128 m]
    float* ws = xs + 64 * 128;           // [64 k][32 n]

    const int mq = tid >> 3;             // 0..63 -> rows {mq, mq+64}
    const int nq = tid & 7;              // 0..7  -> 4 n cols
    float acc[2][4];
#pragma unroll
    for (int i = 0; i < 2; i++)
#pragma unroll
        for (int j = 0; j < 4; j++) acc[i][j] = 0.f;

    for (int kb = 0; kb < KD; kb += 64) {
        __syncthreads();
#pragma unroll
        for (int j = 0; j < 4; j++) {
            const int u = j * 512 + tid;            // 2048 float4 slots
            const int row = u >> 4, kq4 = u & 15;   // row 0..127, k-quad
            float4 v = *(const float4*)(X + (m0 + row) * KD + kb + 4 * kq4);
            xs[(4 * kq4 + 0) * 128 + row] = v.x;
            xs[(4 * kq4 + 1) * 128 + row] = v.y;
            xs[(4 * kq4 + 2) * 128 + row] = v.z;
            xs[(4 * kq4 + 3) * 128 + row] = v.w;
        }
        if (tid < 512) {
            const int row = tid >> 3, nq4 = tid & 7;  // k row, n-quad
            float4 v = *(const float4*)(W + (kb + row) * ND + n0 + 4 * nq4);
            *(float4*)&ws[row * 32 + 4 * nq4] = v;
        }
        __syncthreads();

#pragma unroll 8
        for (int k = 0; k < 64; k++) {
            float a0 = xs[k * 128 + mq];
            float a1 = xs[k * 128 + mq + 64];
            float4 b = *(float4*)&ws[k * 32 + 4 * nq];
            acc[0][0] += a0 * b.x; acc[0][1] += a0 * b.y;
            acc[0][2] += a0 * b.z; acc[0][3] += a0 * b.w;
            acc[1][0] += a1 * b.x; acc[1][1] += a1 * b.y;
            acc[1][2] += a1 * b.z; acc[1][3] += a1 * b.w;
        }
    }

    const float4 bb = *(const float4*)(Bias + n0 + 4 * nq);
#pragma unroll
    for (int i = 0; i < 2; i++) {
        float4 r;
        r.x = acc[i][0] + bb.x;
        r.y = acc[i][1] + bb.y;
        r.z = acc[i][2] + bb.z;
        r.w = acc[i][3] + bb.w;
        *(float4*)(Y + (m0 + mq + 64 * i) * ND + n0 + 4 * nq) = r;
    }
#endif
}

extern "C" void kernel_launch(void* const* d_in, const int* in_sizes, int n_in,
                              void* d_out, int out_size) {
    const float* x = (const float*)d_in[0];  // [512, 512]
    const float* w = (const float*)d_in[1];  // [512, 512]
    const float* b = (const float*)d_in[2];  // [512]
    float* y = (float*)d_out;                // [512, 512]

    static bool attr_done = false;
    if (!attr_done) {
        cudaFuncSetAttribute(gemm_kernel,
                             cudaFuncAttributeMaxDynamicSharedMemorySize,
                             SMEM_DYN);
        attr_done = true;
    }

    convert_kernel<<<128, 256>>>(x, w);
    dim3 grid(ND / 32, MD / 128);            // (16, 4) = 64 CTAs
    gemm_kernel<<<grid, 512, SMEM_DYN>>>(x, w, b, y);
}

// round 6
// speedup vs baseline: 1.6774x; 1.0151x over previous
#include <cuda_runtime.h>
#include <cuda_bf16.h>
#include <cstdint>

// ---------------------------------------------------------------------------
// MemristiveLinear collapses exactly to  y = x @ w + b  (512x512x512 fp32).
//
// ONE fused tcgen05 kernel (no convert kernel, no global scratch):
//   split-precision bf16:  x = xh+xl, w = wh+wl;  y ~= xh@wh + xh@wl + xl@wh
//   - 64 CTAs: M=128 x N=32 tiles (idesc == validated 0x8080490 constant)
//   - prologue: convert ALL of this CTA's W slice (512k x 32n) into 8
//     resident smem chunk-tiles (hi+lo, 64 KB)
//   - mainloop: 8 K-chunks of 64; A fp32 LDG -> register split -> bf16 STS
//     into a 4-deep buffer ring; buffer-reuse mbarrier waits reference
//     chunk c-4 (long complete -> fast-path), commit latency off the
//     critical path
//   - 12 MMA dispatches/chunk (4 K-steps x 3 precision passes), TMEM acc
//   - epilogue: LDTM x32 + bias + STG
// tcgen05 asm guarded for the arch-specific pass; generic compute_103 pass
// compiles a correct fp32 fallback (never runs; driver picks sm_103a cubin).
// ---------------------------------------------------------------------------

#if defined(__CUDA_ARCH_FEAT_SM103_ALL) || defined(__CUDA_ARCH_FEAT_SM100_ALL) || \
    defined(__CUDA_ARCH_FEAT_SM101_ALL) || defined(__CUDA_ARCH_SPECIFIC__) ||     \
    defined(__CUDA_ARCH_FAMILY_SPECIFIC__)
#define TC_OK 1
#else
#define TC_OK 0
#endif

#define MD 512
#define ND 512
#define KD 512

#define SWZ(o) ((o) ^ (((o) >> 3) & 0x70))
#define DESC_BASE 0x4000404000010000ull
#define MK_DESC(addr) (DESC_BASE | (((unsigned long long)((addr) >> 4)) & 0x3FFF))
// kind::f16 idesc: F32 acc, BF16 a/b, M=128, N=32  (== test_mma.cu 0x8080490)
#define IDESC ((1u << 4) | (1u << 7) | (1u << 10) | (4u << 17) | (8u << 24))

// smem map (relative to 1024-aligned base):
//   0: tmem ptr | 8,16,24,32: mbar[4] | 256: bias[32]
//   1024          : WH  8 chunk-tiles x 4096            (32 KB)
//   1024+32768    : WL  8 chunk-tiles x 4096            (32 KB)
//   66560         : A ring, 4 bufs x {Ah 16K, Al 16K}  (128 KB)
#define OFF_WH 1024
#define OFF_WL (1024 + 32768)
#define OFF_A 66560
#define ABUF_STRIDE 32768
#define SMEM_DYN (OFF_A + 4 * ABUF_STRIDE + 1024)  // 198656

__device__ __forceinline__ uint32_t s2u(const void* p) {
    uint32_t a;
    asm("{ .reg .u64 t; cvta.to.shared.u64 t, %1; cvt.u32.u64 %0, t; }"
        : "=r"(a) : "l"(p));
    return a;
}

// Split two fp32 into packed bf16x2 hi + lo (exact two-term split per lane).
__device__ __forceinline__ void split2(float a, float b, unsigned& h,
                                       unsigned& l) {
    unsigned hp;
    asm("cvt.rn.bf16x2.f32 %0, %1, %2;" : "=r"(hp) : "f"(b), "f"(a));
    float fa = __uint_as_float(hp << 16);
    float fb = __uint_as_float(hp & 0xffff0000u);
    float ra = a - fa;
    float rb = b - fb;
    asm("cvt.rn.bf16x2.f32 %0, %1, %2;" : "=r"(l) : "f"(rb), "f"(ra));
    h = hp;
}

#if TC_OK
__device__ __forceinline__ void mma_f16_ss(uint32_t d, unsigned long long ad,
                                           unsigned long long bd,
                                           uint32_t idesc, uint32_t en) {
    asm volatile(
        "{\n\t.reg .pred p;\n\tsetp.ne.u32 p, %5, 0;\n\t"
        "tcgen05.mma.cta_group::1.kind::f16 [%0], %1, %2, %3, {%4, %4, %4, %4}, p;\n\t}"
        :: "r"(d), "l"(ad), "l"(bd), "r"(idesc), "r"(0u), "r"(en)
        : "memory");
}

#define MBAR_INIT(a) \
    asm volatile("mbarrier.init.shared.b64 [%0], %1;" :: "r"(a), "r"(1u) : "memory")

#define MBAR_WAITP(a, ph) do {                                                \
    unsigned _m = (a), _p = (ph), _d;                                         \
    asm volatile("{\n\t.reg .pred p;\n\t"                                     \
        "mbarrier.try_wait.parity.acquire.cta.shared::cta.b64 p, [%1], %2;\n\t" \
        "selp.b32 %0, 1, 0, p;\n\t}" : "=r"(_d) : "r"(_m), "r"(_p) : "memory"); \
    if (!_d) {                                                                \
        asm volatile("{\n\t.reg .pred P1;\n\t"                                \
            "WL_%=:\n\t"                                                      \
            "mbarrier.try_wait.parity.acquire.cta.shared::cta.b64 P1, [%0], %1, 0x989680;\n\t" \
            "@P1 bra.uni WD_%=;\n\t"                                          \
            "bra.uni WL_%=;\n\t"                                              \
            "WD_%=:\n\t}" :: "r"(_m), "r"(_p) : "memory");                    \
    }                                                                         \
} while (0)

#define TC_COMMIT(a) \
    asm volatile("tcgen05.commit.cta_group::1.mbarrier::arrive::one.shared::cluster.b64 [%0];" \
                 :: "r"(a) : "memory")

#define LDTM_X32(r, addr)                                                     \
    asm volatile("tcgen05.ld.sync.aligned.32x32b.x32.b32 "                    \
        "{%0, %1, %2, %3, %4, %5, %6, %7, "                                   \
        " %8, %9, %10, %11, %12, %13, %14, %15, "                             \
        " %16, %17, %18, %19, %20, %21, %22, %23, "                           \
        " %24, %25, %26, %27, %28, %29, %30, %31}, [%32];"                    \
        : "=r"((r)[0]),  "=r"((r)[1]),  "=r"((r)[2]),  "=r"((r)[3]),          \
          "=r"((r)[4]),  "=r"((r)[5]),  "=r"((r)[6]),  "=r"((r)[7]),          \
          "=r"((r)[8]),  "=r"((r)[9]),  "=r"((r)[10]), "=r"((r)[11]),         \
          "=r"((r)[12]), "=r"((r)[13]), "=r"((r)[14]), "=r"((r)[15]),         \
          "=r"((r)[16]), "=r"((r)[17]), "=r"((r)[18]), "=r"((r)[19]),         \
          "=r"((r)[20]), "=r"((r)[21]), "=r"((r)[22]), "=r"((r)[23]),         \
          "=r"((r)[24]), "=r"((r)[25]), "=r"((r)[26]), "=r"((r)[27]),         \
          "=r"((r)[28]), "=r"((r)[29]), "=r"((r)[30]), "=r"((r)[31])          \
        : "r"(addr))
#endif  // TC_OK

__global__ __launch_bounds__(512, 1)
void gemm_kernel(const float* __restrict__ X, const float* __restrict__ W,
                 const float* __restrict__ Bias, float* __restrict__ Y) {
    extern __shared__ char dsm[];
    const int tid = threadIdx.x;
    const int n0 = blockIdx.x * 32;
    const int m0 = blockIdx.y * 128;

#if TC_OK
    const uint32_t raw = s2u(dsm);
    const uint32_t base = (raw + 1023u) & ~1023u;
    char* dbase = dsm + (base - raw);

    const int wid = tid >> 5;
    const int lid = tid & 31;

    float* bias_s = (float*)(dbase + 256);
    if (tid < 8)
        ((float4*)bias_s)[tid] = ((const float4*)(Bias + n0))[tid];

    if (wid == 0)
        asm volatile(
            "tcgen05.alloc.cta_group::1.sync.aligned.shared::cta.b32 [%0], %1;"
            :: "r"(base), "r"(64u) : "memory");
    if (tid == 0) {
#pragma unroll
        for (int i = 0; i < 4; i++) MBAR_INIT(base + 8 + 8 * i);
    }
    __syncthreads();
    uint32_t tmem;
    asm("ld.shared.b32 %0, [%1];" : "=r"(tmem) : "r"(base));

    // ---- A loader geometry: 2048 float4 slots, 4 per thread -------------
    // slot u = j*512 + tid -> row m = u>>4 (0..127), kq = u&15 (8B group)
    const int am[4] = {(0 * 512 + tid) >> 4, (1 * 512 + tid) >> 4,
                       (2 * 512 + tid) >> 4, (3 * 512 + tid) >> 4};
    const int akq = tid & 15;
    int aoff[4];
#pragma unroll
    for (int j = 0; j < 4; j++) aoff[j] = SWZ(am[j] * 128 + akq * 8);

    float4 xr[4];
#define GLOAD_A(c)                                                           \
    do {                                                                     \
        _Pragma("unroll")                                                    \
        for (int j = 0; j < 4; j++)                                          \
            xr[j] = *(const float4*)(X + (m0 + am[j]) * KD + (c) * 64 +      \
                                     4 * akq);                               \
    } while (0)

    // Kick off chunk-0 A loads so their latency hides under the W prologue.
    GLOAD_A(0);

    // ---- W prologue: convert the whole [512k x 32n] slice ---------------
    // thread -> n = tid>>4, kq = tid&15; per chunk 4 scalar loads (k=4kq+i)
    {
        const int wn = tid >> 4;
        const int wkq = tid & 15;
        const int woff = SWZ(wn * 128 + wkq * 8);
#pragma unroll
        for (int c = 0; c < 8; c++) {
            const float* wp = W + (c * 64 + wkq * 4) * ND + n0 + wn;
            float w0 = wp[0 * ND], w1 = wp[1 * ND], w2 = wp[2 * ND],
                  w3 = wp[3 * ND];
            unsigned h01, l01, h23, l23;
            split2(w0, w1, h01, l01);
            split2(w2, w3, h23, l23);
            *(uint2*)(dbase + OFF_WH + c * 4096 + woff) = make_uint2(h01, h23);
            *(uint2*)(dbase + OFF_WL + c * 4096 + woff) = make_uint2(l01, l23);
        }
    }

    int finalph = 0;
#pragma unroll
    for (int c = 0; c < 8; c++) {
        const int buf = c & 3;
        const uint32_t abufb = base + OFF_A + buf * ABUF_STRIDE;
        char* abufp = dbase + OFF_A + buf * ABUF_STRIDE;

        // Buffer reuse guard: MMA(c-4) complete. Far in the past -> fast path.
        if (c >= 4) MBAR_WAITP(base + 8 + 8 * buf, 0);

        // Convert + stage chunk c (fp32 loaded last iteration).
#pragma unroll
        for (int j = 0; j < 4; j++) {
            unsigned h01, l01, h23, l23;
            split2(xr[j].x, xr[j].y, h01, l01);
            split2(xr[j].z, xr[j].w, h23, l23);
            *(uint2*)(abufp + aoff[j]) = make_uint2(h01, h23);
            *(uint2*)(abufp + 16384 + aoff[j]) = make_uint2(l01, l23);
        }

        // Prefetch next chunk's fp32 while fence/sync/MMA run.
        if (c + 1 < 8) GLOAD_A(c + 1);

        asm volatile("fence.proxy.async.shared::cta;" ::: "memory");
        __syncthreads();

        if (tid == 0) {
            const unsigned long long ah = MK_DESC(abufb);
            const unsigned long long al = MK_DESC(abufb + 16384);
            const unsigned long long bh = MK_DESC(base + OFF_WH + c * 4096);
            const unsigned long long bl = MK_DESC(base + OFF_WL + c * 4096);
#pragma unroll
            for (int ks = 0; ks < 4; ks++) {
                mma_f16_ss(tmem, ah + 2 * ks, bh + 2 * ks, IDESC,
                           (c == 0 && ks == 0) ? 0u : 1u);
                mma_f16_ss(tmem, ah + 2 * ks, bl + 2 * ks, IDESC, 1u);
                mma_f16_ss(tmem, al + 2 * ks, bh + 2 * ks, IDESC, 1u);
            }
            TC_COMMIT(base + 8 + 8 * buf);
        }
        if (c == 7) finalph = 1;  // mbar[3] second arrival -> parity 1
    }

    // Final commit (chunk 7, mbar[3], 2nd use) covers all prior MMAs.
    MBAR_WAITP(base + 8 + 8 * 3, finalph);
    asm volatile("tcgen05.fence::after_thread_sync;" ::: "memory");

    if (wid < 4) {
        uint32_t d0[32];
        LDTM_X32(d0, tmem);
        asm volatile("tcgen05.wait::ld.sync.aligned;" ::: "memory");

        float* yr = Y + (m0 + wid * 32 + lid) * ND + n0;
#pragma unroll
        for (int g = 0; g < 8; g++) {
            float4 bb = *(float4*)&bias_s[4 * g];
            float4 r;
            r.x = __uint_as_float(d0[4 * g + 0]) + bb.x;
            r.y = __uint_as_float(d0[4 * g + 1]) + bb.y;
            r.z = __uint_as_float(d0[4 * g + 2]) + bb.z;
            r.w = __uint_as_float(d0[4 * g + 3]) + bb.w;
            *(float4*)(yr + 4 * g) = r;
        }
    }

    __syncthreads();
    if (wid == 0) {
        asm volatile("tcgen05.relinquish_alloc_permit.cta_group::1.sync.aligned;");
        asm volatile("tcgen05.dealloc.cta_group::1.sync.aligned.b32 %0, %1;"
                     :: "r"(tmem), "r"(64u));
    }
#undef GLOAD_A
#else
    // -------- generic-target fallback: fp32 smem-tiled GEMM (correct) ------
    float* xs = (float*)dsm;             // [64 k][128 m]
    float* ws = xs + 64 * 128;           // [64 k][32 n]

    const int mq = tid >> 3;             // 0..63 -> rows {mq, mq+64}
    const int nq = tid & 7;              // 0..7  -> 4 n cols
    float acc[2][4];
#pragma unroll
    for (int i = 0; i < 2; i++)
#pragma unroll
        for (int j = 0; j < 4; j++) acc[i][j] = 0.f;

    for (int kb = 0; kb < KD; kb += 64) {
        __syncthreads();
#pragma unroll
        for (int j = 0; j < 4; j++) {
            const int u = j * 512 + tid;            // 2048 float4 slots
            const int row = u >> 4, kq4 = u & 15;   // row 0..127, k-quad
            float4 v = *(const float4*)(X + (m0 + row) * KD + kb + 4 * kq4);
            xs[(4 * kq4 + 0) * 128 + row] = v.x;
            xs[(4 * kq4 + 1) * 128 + row] = v.y;
            xs[(4 * kq4 + 2) * 128 + row] = v.z;
            xs[(4 * kq4 + 3) * 128 + row] = v.w;
        }
        {
            const int row = tid >> 3, nq4 = tid & 7;  // k row, n-quad
            float4 v = *(const float4*)(W + (kb + row) * ND + n0 + 4 * nq4);
            *(float4*)&ws[row * 32 + 4 * nq4] = v;
        }
        __syncthreads();

#pragma unroll 8
        for (int k = 0; k < 64; k++) {
            float a0 = xs[k * 128 + mq];
            float a1 = xs[k * 128 + mq + 64];
            float4 b = *(float4*)&ws[k * 32 + 4 * nq];
            acc[0][0] += a0 * b.x; acc[0][1] += a0 * b.y;
            acc[0][2] += a0 * b.z; acc[0][3] += a0 * b.w;
            acc[1][0] += a1 * b.x; acc[1][1] += a1 * b.y;
            acc[1][2] += a1 * b.z; acc[1][3] += a1 * b.w;
        }
    }

    const float4 bb = *(const float4*)(Bias + n0 + 4 * nq);
#pragma unroll
    for (int i = 0; i < 2; i++) {
        float4 r;
        r.x = acc[i][0] + bb.x;
        r.y = acc[i][1] + bb.y;
        r.z = acc[i][2] + bb.z;
        r.w = acc[i][3] + bb.w;
        *(float4*)(Y + (m0 + mq + 64 * i) * ND + n0 + 4 * nq) = r;
    }
#endif
}

extern "C" void kernel_launch(void* const* d_in, const int* in_sizes, int n_in,
                              void* d_out, int out_size) {
    const float* x = (const float*)d_in[0];  // [512, 512]
    const float* w = (const float*)d_in[1];  // [512, 512]
    const float* b = (const float*)d_in[2];  // [512]
    float* y = (float*)d_out;                // [512, 512]

    static bool attr_done = false;
    if (!attr_done) {
        cudaFuncSetAttribute(gemm_kernel,
                             cudaFuncAttributeMaxDynamicSharedMemorySize,
                             SMEM_DYN);
        attr_done = true;
    }

    dim3 grid(ND / 32, MD / 128);            // (16, 4) = 64 CTAs
    gemm_kernel<<<grid, 512, SMEM_DYN>>>(x, w, b, y);
}

// round 7
// speedup vs baseline: 1.9500x; 1.1625x over previous
#include <cuda_runtime.h>
#include <cuda_bf16.h>
#include <cstdint>

// ---------------------------------------------------------------------------
// MemristiveLinear == y = x @ w + b (512^3 fp32), via tcgen05 bf16 split:
//   x = xh+xl, w = wh+wl;  y ~= xh@wh + xh@wl + xl@wh  (+b)
//
// R7: - W converted IN-LOOP with fully coalesced loads (lane = n column,
//       128B per warp row-read); no serial uncoalesced prologue.
//     - 4 K-chunks of 128 using the blocked-atom smem layout + descriptor
//       offsets validated in test_mma_iter.cu ({0,2,4,6} then next atom-col).
//     - A ring 2-deep; W chunk tiles resident (written once, no hazard).
//     - 24 MMA dispatches per chunk (8 K-steps x 3 precision passes).
// tcgen05 asm guarded for arch-specific pass; generic compute_103 pass gets
// a correct fp32 fallback (never runs; driver picks the sm_103a cubin).
// ---------------------------------------------------------------------------

#if defined(__CUDA_ARCH_FEAT_SM103_ALL) || defined(__CUDA_ARCH_FEAT_SM100_ALL) || \
    defined(__CUDA_ARCH_FEAT_SM101_ALL) || defined(__CUDA_ARCH_SPECIFIC__) ||     \
    defined(__CUDA_ARCH_FAMILY_SPECIFIC__)
#define TC_OK 1
#else
#define TC_OK 0
#endif

#define MD 512
#define ND 512
#define KD 512

#define SWZ(o) ((o) ^ (((o) >> 3) & 0x70))
#define DESC_BASE 0x4000404000010000ull
#define MK_DESC(addr) (DESC_BASE | (((unsigned long long)((addr) >> 4)) & 0x3FFF))
// kind::f16 idesc: F32 acc, BF16 a/b, M=128, N=32 (validated in R5/R6)
#define IDESC ((1u << 4) | (1u << 7) | (1u << 10) | (4u << 17) | (8u << 24))

// smem map (relative to 1024-aligned base):
//   0: tmem ptr | 8,16: mbar[2] | 256: bias[32]
//   1024  : WH 4 chunk-tiles x 8192   (32 KB)
//   33792 : WL 4 chunk-tiles x 8192   (32 KB)
//   66560 : A ring, 2 bufs x {Ah 32K, Al 32K} (128 KB)
#define OFF_WH 1024
#define OFF_WL 33792
#define OFF_A 66560
#define ABUF_STRIDE 65536
#define SMEM_DYN (OFF_A + 2 * ABUF_STRIDE + 1024)  // 198656

__device__ __forceinline__ uint32_t s2u(const void* p) {
    uint32_t a;
    asm("{ .reg .u64 t; cvta.to.shared.u64 t, %1; cvt.u32.u64 %0, t; }"
        : "=r"(a) : "l"(p));
    return a;
}

// Split two fp32 into packed bf16x2 hi + lo (a in low half).
__device__ __forceinline__ void split2(float a, float b, unsigned& h,
                                       unsigned& l) {
    unsigned hp;
    asm("cvt.rn.bf16x2.f32 %0, %1, %2;" : "=r"(hp) : "f"(b), "f"(a));
    float fa = __uint_as_float(hp << 16);
    float fb = __uint_as_float(hp & 0xffff0000u);
    float ra = a - fa;
    float rb = b - fb;
    asm("cvt.rn.bf16x2.f32 %0, %1, %2;" : "=r"(l) : "f"(rb), "f"(ra));
    h = hp;
}

#if TC_OK
__device__ __forceinline__ void mma_f16_ss(uint32_t d, unsigned long long ad,
                                           unsigned long long bd,
                                           uint32_t idesc, uint32_t en) {
    asm volatile(
        "{\n\t.reg .pred p;\n\tsetp.ne.u32 p, %5, 0;\n\t"
        "tcgen05.mma.cta_group::1.kind::f16 [%0], %1, %2, %3, {%4, %4, %4, %4}, p;\n\t}"
        :: "r"(d), "l"(ad), "l"(bd), "r"(idesc), "r"(0u), "r"(en)
        : "memory");
}

#define MBAR_INIT(a) \
    asm volatile("mbarrier.init.shared.b64 [%0], %1;" :: "r"(a), "r"(1u) : "memory")

#define MBAR_WAITP(a, ph) do {                                                \
    unsigned _m = (a), _p = (ph), _d;                                         \
    asm volatile("{\n\t.reg .pred p;\n\t"                                     \
        "mbarrier.try_wait.parity.acquire.cta.shared::cta.b64 p, [%1], %2;\n\t" \
        "selp.b32 %0, 1, 0, p;\n\t}" : "=r"(_d) : "r"(_m), "r"(_p) : "memory"); \
    if (!_d) {                                                                \
        asm volatile("{\n\t.reg .pred P1;\n\t"                                \
            "WL_%=:\n\t"                                                      \
            "mbarrier.try_wait.parity.acquire.cta.shared::cta.b64 P1, [%0], %1, 0x989680;\n\t" \
            "@P1 bra.uni WD_%=;\n\t"                                          \
            "bra.uni WL_%=;\n\t"                                              \
            "WD_%=:\n\t}" :: "r"(_m), "r"(_p) : "memory");                    \
    }                                                                         \
} while (0)

#define TC_COMMIT(a) \
    asm volatile("tcgen05.commit.cta_group::1.mbarrier::arrive::one.shared::cluster.b64 [%0];" \
                 :: "r"(a) : "memory")

#define LDTM_X32(r, addr)                                                     \
    asm volatile("tcgen05.ld.sync.aligned.32x32b.x32.b32 "                    \
        "{%0, %1, %2, %3, %4, %5, %6, %7, "                                   \
        " %8, %9, %10, %11, %12, %13, %14, %15, "                             \
        " %16, %17, %18, %19, %20, %21, %22, %23, "                           \
        " %24, %25, %26, %27, %28, %29, %30, %31}, [%32];"                    \
        : "=r"((r)[0]),  "=r"((r)[1]),  "=r"((r)[2]),  "=r"((r)[3]),          \
          "=r"((r)[4]),  "=r"((r)[5]),  "=r"((r)[6]),  "=r"((r)[7]),          \
          "=r"((r)[8]),  "=r"((r)[9]),  "=r"((r)[10]), "=r"((r)[11]),         \
          "=r"((r)[12]), "=r"((r)[13]), "=r"((r)[14]), "=r"((r)[15]),         \
          "=r"((r)[16]), "=r"((r)[17]), "=r"((r)[18]), "=r"((r)[19]),         \
          "=r"((r)[20]), "=r"((r)[21]), "=r"((r)[22]), "=r"((r)[23]),         \
          "=r"((r)[24]), "=r"((r)[25]), "=r"((r)[26]), "=r"((r)[27]),         \
          "=r"((r)[28]), "=r"((r)[29]), "=r"((r)[30]), "=r"((r)[31])          \
        : "r"(addr))
#endif  // TC_OK

__global__ __launch_bounds__(512, 1)
void gemm_kernel(const float* __restrict__ X, const float* __restrict__ W,
                 const float* __restrict__ Bias, float* __restrict__ Y) {
    extern __shared__ char dsm[];
    const int tid = threadIdx.x;
    const int n0 = blockIdx.x * 32;
    const int m0 = blockIdx.y * 128;

#if TC_OK
    const uint32_t raw = s2u(dsm);
    const uint32_t base = (raw + 1023u) & ~1023u;
    char* dbase = dsm + (base - raw);

    const int wid = tid >> 5;
    const int lid = tid & 31;

    float* bias_s = (float*)(dbase + 256);
    if (tid < 8)
        ((float4*)bias_s)[tid] = ((const float4*)(Bias + n0))[tid];

    if (wid == 0)
        asm volatile(
            "tcgen05.alloc.cta_group::1.sync.aligned.shared::cta.b32 [%0], %1;"
            :: "r"(base), "r"(64u) : "memory");
    if (tid == 0) {
        MBAR_INIT(base + 8);
        MBAR_INIT(base + 16);
    }
    __syncthreads();
    uint32_t tmem;
    asm("ld.shared.b32 %0, [%1];" : "=r"(tmem) : "r"(base));

    // ---- A geometry: chunk = 128m x 128k fp32 = 4096 float4, 8/thread ----
    // slot u = j*512+tid: row = u>>5 (all j share row group), kq = tid&31
    const int arow = tid >> 5;           // + j*16
    const int akq = tid & 31;            // 4-float k group (0..31)
    int aoff[8];
#pragma unroll
    for (int j = 0; j < 8; j++) {
        const int row = j * 16 + arow;
        const int ar = row >> 3, ir = row & 7;
        const int ac = akq >> 4, icq = akq & 15;
        aoff[j] = SWZ((ar + ac * 16) * 1024 + ir * 128 + icq * 8);
    }

    // ---- W geometry: lane = n col (coalesced), wid = k-pair --------------
    const int wn = tid & 31;             // n within tile
    const int wkp = tid >> 5;            // k-pair base (0..15), 4 passes
    int woff[4];
#pragma unroll
    for (int p = 0; p < 4; p++) {
        const int kl = p * 32 + 2 * wkp;
        const int ac = kl >> 6, ic = kl & 63;
        woff[p] = SWZ(((wn >> 3) + ac * 4) * 1024 + (wn & 7) * 128 + ic * 2);
    }

    float4 xr[8];
    float wr[8];

#define GLOAD(c)                                                             \
    do {                                                                     \
        _Pragma("unroll")                                                    \
        for (int j = 0; j < 8; j++)                                          \
            xr[j] = *(const float4*)(X + (m0 + j * 16 + arow) * KD +         \
                                     (c) * 128 + 4 * akq);                   \
        _Pragma("unroll")                                                    \
        for (int p = 0; p < 4; p++) {                                        \
            const int kg = (c) * 128 + p * 32 + 2 * wkp;                     \
            wr[2 * p]     = W[(size_t)kg * ND + n0 + wn];                    \
            wr[2 * p + 1] = W[(size_t)(kg + 1) * ND + n0 + wn];              \
        }                                                                    \
    } while (0)

    GLOAD(0);

#pragma unroll
    for (int c = 0; c < 4; c++) {
        const int buf = c & 1;
        const uint32_t abufb = base + OFF_A + buf * ABUF_STRIDE;
        char* abufp = dbase + OFF_A + buf * ABUF_STRIDE;

        // Buffer reuse guard: MMA(c-2) complete.
        if (c >= 2) MBAR_WAITP(base + 8 + 8 * buf, 0);

        // Stage A chunk (bf16 hi/lo, blocked-atom layout).
#pragma unroll
        for (int j = 0; j < 8; j++) {
            unsigned h01, l01, h23, l23;
            split2(xr[j].x, xr[j].y, h01, l01);
            split2(xr[j].z, xr[j].w, h23, l23);
            *(uint2*)(abufp + aoff[j]) = make_uint2(h01, h23);
            *(uint2*)(abufp + 32768 + aoff[j]) = make_uint2(l01, l23);
        }
        // Stage W chunk.
        {
            char* whp = dbase + OFF_WH + c * 8192;
            char* wlp = dbase + OFF_WL + c * 8192;
#pragma unroll
            for (int p = 0; p < 4; p++) {
                unsigned h, l;
                split2(wr[2 * p], wr[2 * p + 1], h, l);
                *(unsigned*)(whp + woff[p]) = h;
                *(unsigned*)(wlp + woff[p]) = l;
            }
        }

        if (c + 1 < 4) GLOAD(c + 1);

        asm volatile("fence.proxy.async.shared::cta;" ::: "memory");
        __syncthreads();

        if (tid == 0) {
            const unsigned long long ah = MK_DESC(abufb);
            const unsigned long long al = MK_DESC(abufb + 32768);
            const unsigned long long bh = MK_DESC(base + OFF_WH + c * 8192);
            const unsigned long long bl = MK_DESC(base + OFF_WL + c * 8192);
#pragma unroll
            for (int ks = 0; ks < 8; ks++) {
                const int ao = (ks < 4) ? 2 * ks : 1024 + 2 * (ks - 4);
                const int bo = (ks < 4) ? 2 * ks : 256 + 2 * (ks - 4);
                mma_f16_ss(tmem, ah + ao, bh + bo, IDESC,
                           (c == 0 && ks == 0) ? 0u : 1u);
                mma_f16_ss(tmem, ah + ao, bl + bo, IDESC, 1u);
                mma_f16_ss(tmem, al + ao, bh + bo, IDESC, 1u);
            }
            TC_COMMIT(base + 8 + 8 * buf);
        }
    }

    // All MMAs done when both buffers' second commits land (parity 1).
    MBAR_WAITP(base + 8, 1);
    MBAR_WAITP(base + 16, 1);
    asm volatile("tcgen05.fence::after_thread_sync;" ::: "memory");

    if (wid < 4) {
        uint32_t d0[32];
        LDTM_X32(d0, tmem);
        asm volatile("tcgen05.wait::ld.sync.aligned;" ::: "memory");

        float* yr = Y + (m0 + wid * 32 + lid) * ND + n0;
#pragma unroll
        for (int g = 0; g < 8; g++) {
            float4 bb = *(float4*)&bias_s[4 * g];
            float4 r;
            r.x = __uint_as_float(d0[4 * g + 0]) + bb.x;
            r.y = __uint_as_float(d0[4 * g + 1]) + bb.y;
            r.z = __uint_as_float(d0[4 * g + 2]) + bb.z;
            r.w = __uint_as_float(d0[4 * g + 3]) + bb.w;
            *(float4*)(yr + 4 * g) = r;
        }
    }

    __syncthreads();
    if (wid == 0) {
        asm volatile("tcgen05.relinquish_alloc_permit.cta_group::1.sync.aligned;");
        asm volatile("tcgen05.dealloc.cta_group::1.sync.aligned.b32 %0, %1;"
                     :: "r"(tmem), "r"(64u));
    }
#undef GLOAD
#else
    // -------- generic-target fallback: fp32 smem-tiled GEMM (correct) ------
    float* xs = (float*)dsm;             // [64 k][128 m]
    float* ws = xs + 64 * 128;           // [64 k][32 n]

    const int mq = tid >> 3;             // 0..63 -> rows {mq, mq+64}
    const int nq = tid & 7;              // 0..7  -> 4 n cols
    float acc[2][4];
#pragma unroll
    for (int i = 0; i < 2; i++)
#pragma unroll
        for (int j = 0; j < 4; j++) acc[i][j] = 0.f;

    for (int kb = 0; kb < KD; kb += 64) {
        __syncthreads();
#pragma unroll
        for (int j = 0; j < 4; j++) {
            const int u = j * 512 + tid;            // 2048 float4 slots
            const int row = u >> 4, kq4 = u & 15;   // row 0..127, k-quad
            float4 v = *(const float4*)(X + (m0 + row) * KD + kb + 4 * kq4);
            xs[(4 * kq4 + 0) * 128 + row] = v.x;
            xs[(4 * kq4 + 1) * 128 + row] = v.y;
            xs[(4 * kq4 + 2) * 128 + row] = v.z;
            xs[(4 * kq4 + 3) * 128 + row] = v.w;
        }
        {
            const int row = tid >> 3, nq4 = tid & 7;  // k row, n-quad
            float4 v = *(const float4*)(W + (kb + row) * ND + n0 + 4 * nq4);
            *(float4*)&ws[row * 32 + 4 * nq4] = v;
        }
        __syncthreads();

#pragma unroll 8
        for (int k = 0; k < 64; k++) {
            float a0 = xs[k * 128 + mq];
            float a1 = xs[k * 128 + mq + 64];
            float4 b = *(float4*)&ws[k * 32 + 4 * nq];
            acc[0][0] += a0 * b.x; acc[0][1] += a0 * b.y;
            acc[0][2] += a0 * b.z; acc[0][3] += a0 * b.w;
            acc[1][0] += a1 * b.x; acc[1][1] += a1 * b.y;
            acc[1][2] += a1 * b.z; acc[1][3] += a1 * b.w;
        }
    }

    const float4 bb = *(const float4*)(Bias + n0 + 4 * nq);
#pragma unroll
    for (int i = 0; i < 2; i++) {
        float4 r;
        r.x = acc[i][0] + bb.x;
        r.y = acc[i][1] + bb.y;
        r.z = acc[i][2] + bb.z;
        r.w = acc[i][3] + bb.w;
        *(float4*)(Y + (m0 + mq + 64 * i) * ND + n0 + 4 * nq) = r;
    }
#endif
}

extern "C" void kernel_launch(void* const* d_in, const int* in_sizes, int n_in,
                              void* d_out, int out_size) {
    const float* x = (const float*)d_in[0];  // [512, 512]
    const float* w = (const float*)d_in[1];  // [512, 512]
    const float* b = (const float*)d_in[2];  // [512]
    float* y = (float*)d_out;                // [512, 512]

    static bool attr_done = false;
    if (!attr_done) {
        cudaFuncSetAttribute(gemm_kernel,
                             cudaFuncAttributeMaxDynamicSharedMemorySize,
                             SMEM_DYN);
        attr_done = true;
    }

    dim3 grid(ND / 32, MD / 128);            // (16, 4) = 64 CTAs
    gemm_kernel<<<grid, 512, SMEM_DYN>>>(x, w, b, y);
}